// round 3
// baseline (speedup 1.0000x reference)
#include <cuda_runtime.h>
#include <cuda_bf16.h>

// Radius-neighbor mean pooling, fully fused into ONE persistent kernel:
//   phase 0: zero per-cell counters
//   phase 1: bin input points (pos + 8 channel values packed per 48B record)
//   phase 2: warp-per-output 27-cell gather + mean
// separated by software grid barriers (148 CTAs x 1024 thr, 1 CTA/SM,
// guaranteed co-resident on sm_103a). The barrier counter is cumulative and
// self-resetting (last CTA of the final arrival writes 0), so every graph
// replay starts from the same state.

#define RADIUS   0.05f
#define R2       (RADIUS * RADIUS)
#define GRID     20
#define NCELLS   (GRID * GRID * GRID)   // 8000
#define CAP      64                     // lambda ~2.05 pts/cell; P(>=64) ~ 1e-63
#define BCH      8                      // channels (B)
#define EFLOATS  12                     // 3 pos + 8 ch + 1 pad = 48 bytes

#define NCTA     148
#define NTHR     1024

__device__ int   g_counts[NCELLS];
__device__ float g_bins[NCELLS * CAP * EFLOATS];
__device__ int   g_bar;                 // zero at module load; self-reset each run

__device__ __forceinline__ int cell_coord(float p) {
    int c = (int)(p * (float)GRID);
    if (c < 0) c = 0;
    if (c > GRID - 1) c = GRID - 1;
    return c;
}

// Grid barrier: cumulative counter, per-phase target. Thread 0 of each CTA
// arrives (after a device fence publishing this CTA's writes) and spins until
// all CTAs of this phase have arrived; __syncthreads fans the release out.
__device__ __forceinline__ void grid_barrier(int target) {
    __syncthreads();
    if (threadIdx.x == 0) {
        __threadfence();
        atomicAdd(&g_bar, 1);
        while (atomicAdd(&g_bar, 0) < target) { }
        __threadfence();
    }
    __syncthreads();
}

__global__ void __launch_bounds__(NTHR, 1)
fused_kernel(const float* __restrict__ x,
             const float* __restrict__ ipos,
             const float* __restrict__ opos,
             float* __restrict__ out,
             int n_in, int n_out) {
    int tid  = blockIdx.x * NTHR + threadIdx.x;
    int nthr = NCTA * NTHR;

    // ---------------- phase 0: zero counters ----------------
    for (int c = tid; c < NCELLS; c += nthr) g_counts[c] = 0;

    grid_barrier(NCTA);

    // ---------------- phase 1: bin points -------------------
    for (int i = tid; i < n_in; i += nthr) {
        float px = ipos[i * 3 + 0];
        float py = ipos[i * 3 + 1];
        float pz = ipos[i * 3 + 2];
        int cell = (cell_coord(px) * GRID + cell_coord(py)) * GRID + cell_coord(pz);

        int slot = atomicAdd(&g_counts[cell], 1);
        if (slot < CAP) {
            float4* e = (float4*)&g_bins[(cell * CAP + slot) * EFLOATS];
            e[0] = make_float4(px, py, pz, x[0 * n_in + i]);
            e[1] = make_float4(x[1 * n_in + i], x[2 * n_in + i],
                               x[3 * n_in + i], x[4 * n_in + i]);
            e[2] = make_float4(x[5 * n_in + i], x[6 * n_in + i],
                               x[7 * n_in + i], 0.0f);
        }
    }

    grid_barrier(2 * NCTA);

    // ---------------- phase 2: gather -----------------------
    int warp       = tid >> 5;
    int lane       = threadIdx.x & 31;
    int total_warps = nthr >> 5;

    for (int o = warp; o < n_out; o += total_warps) {
        float ox = opos[o * 3 + 0];
        float oy = opos[o * 3 + 1];
        float oz = opos[o * 3 + 2];

        float cnt = 0.0f;
        float s[BCH];
#pragma unroll
        for (int b = 0; b < BCH; b++) s[b] = 0.0f;

        if (lane < 27) {
            int cx = cell_coord(ox) + (lane / 9) - 1;
            int cy = cell_coord(oy) + ((lane / 3) % 3) - 1;
            int cz = cell_coord(oz) + (lane % 3) - 1;
            if (cx >= 0 && cx < GRID && cy >= 0 && cy < GRID && cz >= 0 && cz < GRID) {
                int cell = (cx * GRID + cy) * GRID + cz;
                int c = g_counts[cell];
                if (c > CAP) c = CAP;
                const float4* base = (const float4*)&g_bins[cell * CAP * EFLOATS];
                for (int t = 0; t < c; t++) {
                    float4 e0 = base[t * 3 + 0];
                    float4 e1 = base[t * 3 + 1];
                    float4 e2 = base[t * 3 + 2];
                    float dx = ox - e0.x;
                    float dy = oy - e0.y;
                    float dz = oz - e0.z;
                    float d2 = fmaf(dx, dx, fmaf(dy, dy, dz * dz));
                    if (d2 <= R2) {
                        cnt  += 1.0f;
                        s[0] += e0.w;
                        s[1] += e1.x;  s[2] += e1.y;  s[3] += e1.z;  s[4] += e1.w;
                        s[5] += e2.x;  s[6] += e2.y;  s[7] += e2.z;
                    }
                }
            }
        }

#pragma unroll
        for (int off = 16; off > 0; off >>= 1) {
            cnt += __shfl_xor_sync(0xFFFFFFFFu, cnt, off);
#pragma unroll
            for (int b = 0; b < BCH; b++)
                s[b] += __shfl_xor_sync(0xFFFFFFFFu, s[b], off);
        }

        if (lane == 0) {
            float dem = cnt > 0.0f ? cnt : 1.0f;
            float inv = 1.0f / dem;
#pragma unroll
            for (int b = 0; b < BCH; b++)
                out[b * n_out + o] = s[b] * inv;
        }
    }

    // ---------------- epilogue: reset barrier counter -------
    // Third cumulative arrival; the very last CTA restores g_bar = 0 so the
    // next graph replay starts from the same state. No one reads g_bar after
    // the phase-2 barrier, so this cannot race with a spinner.
    __syncthreads();
    if (threadIdx.x == 0) {
        int old = atomicAdd(&g_bar, 1);
        if (old == 3 * NCTA - 1) atomicExch(&g_bar, 0);
    }
}

// ---------------------------------------------------------------------------
extern "C" void kernel_launch(void* const* d_in, const int* in_sizes, int n_in_arr,
                              void* d_out, int out_size) {
    const float* x    = (const float*)d_in[0];   // [B, n_in]
    const float* ipos = (const float*)d_in[1];   // [n_in, 3]
    const float* opos = (const float*)d_in[2];   // [n_out, 3]
    float* out = (float*)d_out;                  // [B, n_out]

    int n_in  = in_sizes[1] / 3;
    int n_out = in_sizes[2] / 3;

    fused_kernel<<<NCTA, NTHR>>>(x, ipos, opos, out, n_in, n_out);
}